// round 12
// baseline (speedup 1.0000x reference)
#include <cuda_runtime.h>
#include <cuda_bf16.h>
#include <math.h>

// ===========================================================================
// MPConv via mma.sync bf16 (compute_103-safe):
//   node precompute: A = x@W1[0:64], B = x@W1[64:128]+b1 (scalar f32x2,
//     broadcast-LDG rows, no barriers)
//   edge: warp-autonomous 16-edge sub-tiles (mt-split for occupancy):
//     acc = A[i]+B[j] (fragment gather) ; acc += ea@W1e (3-term split-bf16)
//     LN per row (2 quad shfl) + branchless A&S erf GELU
//     GEMM2 g@W2+b2 in two N-halves ; red.global.add.v2 scatter
// ===========================================================================

#define MAXN 100000
#define CH   64
#define ED   32

__device__ float g_A[(size_t)MAXN * CH];
__device__ float g_B[(size_t)MAXN * CH];
__device__ int   g_idx64;

typedef unsigned long long u64;
typedef unsigned int       u32;

__device__ __forceinline__ u64 pk2(float lo, float hi) {
    u64 r; asm("mov.b64 %0, {%1,%2};" : "=l"(r) : "f"(lo), "f"(hi)); return r;
}
__device__ __forceinline__ void unpk2(u64 v, float& lo, float& hi) {
    asm("mov.b64 {%0,%1}, %2;" : "=f"(lo), "=f"(hi) : "l"(v));
}
__device__ __forceinline__ u64 fma2(u64 a, u64 b, u64 c) {
    u64 d; asm("fma.rn.f32x2 %0, %1, %2, %3;" : "=l"(d) : "l"(a), "l"(b), "l"(c));
    return d;
}
__device__ __forceinline__ u64 add2(u64 a, u64 b) {
    u64 d; asm("add.rn.f32x2 %0, %1, %2;" : "=l"(d) : "l"(a), "l"(b));
    return d;
}
__device__ __forceinline__ float hsum2(u64 v) { float a, b; unpk2(v, a, b); return a + b; }

__device__ __forceinline__ void red2(float* p, float x, float y) {
    asm volatile("red.global.add.v2.f32 [%0], {%1,%2};"
                 :: "l"(p), "f"(x), "f"(y) : "memory");
}
__device__ __forceinline__ void split1(float v, __nv_bfloat16& h, __nv_bfloat16& l) {
    h = __float2bfloat16_rn(v);
    l = __float2bfloat16_rn(v - __bfloat162float(h));
}
__device__ __forceinline__ u32 pkbf(__nv_bfloat16 a, __nv_bfloat16 b) {
    __nv_bfloat162 t(a, b); return *(u32*)&t;
}
__device__ __forceinline__ u32 hi_pair(float x, float y) {
    u32 r;
    asm("prmt.b32 %0, %1, %2, 0x7632;"
        : "=r"(r) : "r"(__float_as_uint(x)), "r"(__float_as_uint(y)));
    return r;
}
__device__ __forceinline__ u32 lo_pair(float x, float y) {
    float lx = x - __uint_as_float(__float_as_uint(x) & 0xFFFF0000u);
    float ly = y - __uint_as_float(__float_as_uint(y) & 0xFFFF0000u);
    u32 r;
    asm("cvt.rn.bf16x2.f32 %0, %1, %2;" : "=r"(r) : "f"(ly), "f"(lx));
    return r;
}

// Branchless GELU, A&S 7.1.26 erf (|eps| <= 1.5e-7 abs).
__device__ __forceinline__ float gelu_fast(float x) {
    const float axo = fabsf(x);
    const float ax  = axo * 0.70710678118654752440f;
    float t;
    asm("rcp.approx.f32 %0, %1;" : "=f"(t) : "f"(fmaf(0.3275911f, ax, 1.0f)));
    float p = fmaf(1.061405429f, t, -1.453152027f);
    p = fmaf(p, t, 1.421413741f);
    p = fmaf(p, t, -0.284496736f);
    p = fmaf(p, t, 0.254829592f);
    p = p * t;
    float ex;
    asm("ex2.approx.f32 %0, %1;"
        : "=f"(ex) : "f"(ax * ax * -1.4426950408889634f));
    const float er = fmaf(-p, ex, 1.0f);
    return fmaf(0.5f * axo, er, 0.5f * x);
}

__device__ __forceinline__ void mma16816(float* c, const u32* a, const u32* b) {
    asm volatile(
        "mma.sync.aligned.m16n8k16.row.col.f32.bf16.bf16.f32 "
        "{%0,%1,%2,%3}, {%4,%5,%6,%7}, {%8,%9}, {%0,%1,%2,%3};"
        : "+f"(c[0]), "+f"(c[1]), "+f"(c[2]), "+f"(c[3])
        : "r"(a[0]), "r"(a[1]), "r"(a[2]), "r"(a[3]), "r"(b[0]), "r"(b[1]));
}

// ---------------------------------------------------------------------------
// Node precompute: no smem, no loop barriers; x rows via broadcast LDG.128.
// 256 thr = 2 nodes x {A,B} x 64 ch; 64 weight regs/thread.
// ---------------------------------------------------------------------------
__global__ __launch_bounds__(256) void node_pre_kernel(
    const float* __restrict__ x, const float* __restrict__ W1,
    const float* __restrict__ b1, const int* __restrict__ ei, int n_nodes)
{
    const int t = threadIdx.x;
    const int c   = t & 63;
    const int ab  = (t >> 6) & 1;
    const int grp = t >> 7;

    if (blockIdx.x == 0) {
        int ok = 1;
        for (int q = t; q < 1024; q += blockDim.x)
            if (ei[2 * q + 1] != 0) ok = 0;
        ok = __syncthreads_and(ok);
        if (t == 0) g_idx64 = ok;
    }

    const int kofs = ab ? 64 : 0;
    u64 w[32];
#pragma unroll
    for (int q = 0; q < 32; q++)
        w[q] = pk2(W1[(kofs + 2 * q) * CH + c], W1[(kofs + 2 * q + 1) * CH + c]);
    const float bias = ab ? b1[c] : 0.0f;
    float* dst = ab ? g_B : g_A;

    for (int n0 = blockIdx.x * 2; n0 < n_nodes; n0 += gridDim.x * 2) {
        const int node = n0 + grp;
        if (node < n_nodes) {
            const ulonglong2* xp = (const ulonglong2*)(x + (size_t)node * CH);
            u64 a0 = 0ull, a1 = 0ull;
#pragma unroll
            for (int q = 0; q < 16; q++) {
                ulonglong2 xv = xp[q];          // broadcast within warp
                a0 = fma2(xv.x, w[2 * q],     a0);
                a1 = fma2(xv.y, w[2 * q + 1], a1);
            }
            dst[(size_t)node * CH + c] = hsum2(add2(a0, a1)) + bias;
        }
    }
}

// ---------------------------------------------------------------------------
// Edge kernel: 4 warps/block, each warp owns 32-edge tiles processed as
// two independent 16-edge sub-tiles (register diet -> 4+ blocks/SM).
// ---------------------------------------------------------------------------
__global__ void __launch_bounds__(128, 4) edge_mma_kernel(
    const void* __restrict__ ei_raw,
    const float* __restrict__ ea,
    const float* __restrict__ W1,
    const float* __restrict__ gamma, const float* __restrict__ beta,
    const float* __restrict__ W2, const float* __restrict__ b2,
    float* __restrict__ out, int n_edges, int n_wtiles)
{
    // Weight B-fragment pairs as u64 words: [4*kt+tq][n], row pad 72.
    __shared__ uint2 sW1H64[8][72],  sW1L64[8][72];
    __shared__ uint2 sW2H64[16][72], sW2L64[16][72];
    __shared__ float sgm[64], sbt[64], sb2v[64];

    const int tid = threadIdx.x;
    for (int idx = tid; idx < 64 * 8; idx += 128) {        // W1 edge part
        int n = idx >> 3, kg = idx & 7;
        int kt = kg >> 2, t4 = kg & 3;
        int plo = 8 * kt + t4, phi = plo + 4;
        __nv_bfloat16 ha, la, hb, lb;
        split1(W1[(size_t)(128 + 2 * plo) * CH + n], ha, la);
        split1(W1[(size_t)(128 + 2 * plo + 1) * CH + n], hb, lb);
        u32 Hlo = pkbf(ha, hb), Llo = pkbf(la, lb);
        split1(W1[(size_t)(128 + 2 * phi) * CH + n], ha, la);
        split1(W1[(size_t)(128 + 2 * phi + 1) * CH + n], hb, lb);
        sW1H64[kg][n] = make_uint2(Hlo, pkbf(ha, hb));
        sW1L64[kg][n] = make_uint2(Llo, pkbf(la, lb));
    }
    for (int idx = tid; idx < 64 * 16; idx += 128) {       // W2
        int n = idx >> 4, kg = idx & 15;
        int kt = kg >> 2, t4 = kg & 3;
        int plo = 8 * kt + t4, phi = plo + 4;
        __nv_bfloat16 ha, la, hb, lb;
        split1(W2[(size_t)(2 * plo) * CH + n], ha, la);
        split1(W2[(size_t)(2 * plo + 1) * CH + n], hb, lb);
        u32 Hlo = pkbf(ha, hb), Llo = pkbf(la, lb);
        split1(W2[(size_t)(2 * phi) * CH + n], ha, la);
        split1(W2[(size_t)(2 * phi + 1) * CH + n], hb, lb);
        sW2H64[kg][n] = make_uint2(Hlo, pkbf(ha, hb));
        sW2L64[kg][n] = make_uint2(Llo, pkbf(la, lb));
    }
    if (tid < 64) { sgm[tid] = gamma[tid]; sbt[tid] = beta[tid]; sb2v[tid] = b2[tid]; }
    __syncthreads();

    const int wid = tid >> 5, lane = tid & 31;
    const int q = lane >> 2, tq = lane & 3;
    const int flag64 = g_idx64;
    const long long* ei64 = (const long long*)ei_raw;
    const int*       ei32 = (const int*)ei_raw;
    const int wstep = gridDim.x * 4;

    for (int wt = blockIdx.x * 4 + wid; wt < n_wtiles; wt += wstep) {
        const int eb = wt * 32;

#pragma unroll 1
        for (int mt = 0; mt < 2; mt++) {
            const int rb = eb + 16 * mt;     // sub-tile base edge

            // ---- indices: rows 8*g8 + q ----------------------------------
            int iv[2], jv[2];
#pragma unroll
            for (int g8 = 0; g8 < 2; g8++) {
                int e = rb + 8 * g8 + q; if (e >= n_edges) e = 0;
                if (flag64) { iv[g8] = (int)ei64[e]; jv[g8] = (int)ei64[(size_t)n_edges + e]; }
                else        { iv[g8] = ei32[e];      jv[g8] = ei32[(size_t)n_edges + e]; }
            }

            // ---- acc init = s = A[i]+B[j] (fragment gather) --------------
            float acc[8][4];
            {
                const float2* pa0 = (const float2*)(g_A + (size_t)iv[0] * CH);
                const float2* pb0 = (const float2*)(g_B + (size_t)jv[0] * CH);
                const float2* pa8 = (const float2*)(g_A + (size_t)iv[1] * CH);
                const float2* pb8 = (const float2*)(g_B + (size_t)jv[1] * CH);
#pragma unroll
                for (int nt = 0; nt < 8; nt++) {
                    float2 x0 = pa0[4 * nt + tq], y0 = pb0[4 * nt + tq];
                    float2 x8 = pa8[4 * nt + tq], y8 = pb8[4 * nt + tq];
                    acc[nt][0] = x0.x + y0.x;  acc[nt][1] = x0.y + y0.y;
                    acc[nt][2] = x8.x + y8.x;  acc[nt][3] = x8.y + y8.y;
                }
            }

            // ---- ea A-fragments (fast hi/lo split) -----------------------
            u32 eH[2][4], eL[2][4];
#pragma unroll
            for (int g8 = 0; g8 < 2; g8++) {
                int e = rb + 8 * g8 + q; if (e >= n_edges) e = 0;
                const float2* pe = (const float2*)(ea + (size_t)e * ED);
#pragma unroll
                for (int kt = 0; kt < 2; kt++)
#pragma unroll
                    for (int gr = 0; gr < 2; gr++) {
                        float2 v = pe[8 * kt + 4 * gr + tq];
                        eH[kt][gr * 2 + g8] = hi_pair(v.x, v.y);
                        eL[kt][gr * 2 + g8] = lo_pair(v.x, v.y);
                    }
            }

            // ---- GEMM1: acc += ea @ W1e (3-term split) -------------------
#pragma unroll
            for (int kt = 0; kt < 2; kt++)
#pragma unroll
                for (int nt = 0; nt < 8; nt++) {
                    uint2 BH = sW1H64[4 * kt + tq][8 * nt + q];
                    uint2 BL = sW1L64[4 * kt + tq][8 * nt + q];
                    u32 bH[2] = { BH.x, BH.y };
                    u32 bL[2] = { BL.x, BL.y };
                    mma16816(acc[nt], eH[kt], bH);
                    mma16816(acc[nt], eH[kt], bL);
                    mma16816(acc[nt], eL[kt], bH);
                }

            // ---- LayerNorm stats: quad reduce (2 shfl) per row -----------
            float mean[2], rstd[2];
#pragma unroll
            for (int g8 = 0; g8 < 2; g8++) {
                u64 ssp = 0ull;
#pragma unroll
                for (int nt = 0; nt < 8; nt++) {
                    float v0 = acc[nt][2 * g8], v1 = acc[nt][2 * g8 + 1];
                    ssp = add2(ssp, pk2(v0 + v1, fmaf(v0, v0, v1 * v1)));
                }
                ssp = add2(ssp, __shfl_xor_sync(0xffffffffu, ssp, 1));
                ssp = add2(ssp, __shfl_xor_sync(0xffffffffu, ssp, 2));
                float s, s2; unpk2(ssp, s, s2);
                float mu = s * (1.0f / 64.0f);
                mean[g8] = mu;
                rstd[g8] = rsqrtf(s2 * (1.0f / 64.0f) - mu * mu + 1e-5f);
            }

            // ---- LN + fast GELU + split -> GEMM2 A-fragments -------------
            u32 gh[2][8], gl[2][8];
#pragma unroll
            for (int nt = 0; nt < 8; nt++) {
                float2 gm = *(const float2*)&sgm[8 * nt + 2 * tq];
                float2 bt = *(const float2*)&sbt[8 * nt + 2 * tq];
#pragma unroll
                for (int g8 = 0; g8 < 2; g8++) {
                    float h0 = fmaf((acc[nt][2 * g8]     - mean[g8]) * rstd[g8], gm.x, bt.x);
                    float h1 = fmaf((acc[nt][2 * g8 + 1] - mean[g8]) * rstd[g8], gm.y, bt.y);
                    float e0 = gelu_fast(h0);
                    float e1 = gelu_fast(h1);
                    gh[g8][nt] = hi_pair(e0, e1);
                    gl[g8][nt] = lo_pair(e0, e1);
                }
            }

            // ---- GEMM2 + scatter in two sequential N-halves --------------
#pragma unroll 1
            for (int half = 0; half < 2; half++) {
                float acc2[4][4];
#pragma unroll
                for (int n4 = 0; n4 < 4; n4++) {
                    float2 b2p = *(const float2*)&sb2v[8 * (half * 4 + n4) + 2 * tq];
                    acc2[n4][0] = b2p.x; acc2[n4][1] = b2p.y;
                    acc2[n4][2] = b2p.x; acc2[n4][3] = b2p.y;
                }
#pragma unroll
                for (int kt = 0; kt < 4; kt++) {
                    u32 aH[4] = { gh[0][2 * kt], gh[1][2 * kt],
                                  gh[0][2 * kt + 1], gh[1][2 * kt + 1] };
                    u32 aL[4] = { gl[0][2 * kt], gl[1][2 * kt],
                                  gl[0][2 * kt + 1], gl[1][2 * kt + 1] };
#pragma unroll
                    for (int n4 = 0; n4 < 4; n4++) {
                        int nr = 8 * (half * 4 + n4) + q;
                        uint2 BH = sW2H64[4 * kt + tq][nr];
                        uint2 BL = sW2L64[4 * kt + tq][nr];
                        u32 bH[2] = { BH.x, BH.y };
                        u32 bL[2] = { BL.x, BL.y };
                        mma16816(acc2[n4], aH, bH);
                        mma16816(acc2[n4], aH, bL);
                        mma16816(acc2[n4], aL, bH);
                    }
                }
#pragma unroll
                for (int g8 = 0; g8 < 2; g8++) {
                    int e = rb + 8 * g8 + q;
                    if (e < n_edges) {
                        float* op = out + (size_t)jv[g8] * CH + 2 * tq;
#pragma unroll
                        for (int n4 = 0; n4 < 4; n4++)
                            red2(op + 8 * (half * 4 + n4),
                                 acc2[n4][2 * g8], acc2[n4][2 * g8 + 1]);
                    }
                }
            }
        }
    }
}

// ---------------------------------------------------------------------------
// Inputs: x[N,64] f32, edge_index[2,E] (i32/i64), edge_attr[E,32] f32,
// W1[160,64], b1[64], gamma[64], beta[64], W2[64,64], b2[64]. Out [N,64] f32.
// ---------------------------------------------------------------------------
extern "C" void kernel_launch(void* const* d_in, const int* in_sizes, int n_in,
                              void* d_out, int out_size)
{
    const float* x     = (const float*)d_in[0];
    const void*  ei    = d_in[1];
    const float* ea    = (const float*)d_in[2];
    const float* W1    = (const float*)d_in[3];
    const float* b1    = (const float*)d_in[4];
    const float* gamma = (const float*)d_in[5];
    const float* beta  = (const float*)d_in[6];
    const float* W2    = (const float*)d_in[7];
    const float* b2    = (const float*)d_in[8];
    float* out = (float*)d_out;

    const int n_nodes  = in_sizes[0] / CH;
    const int n_edges  = in_sizes[2] / ED;
    const int n_wtiles = (n_edges + 31) / 32;
    if (n_nodes > MAXN) return;

    cudaMemsetAsync(d_out, 0, (size_t)out_size * sizeof(float));

    node_pre_kernel<<<296, 256>>>(x, W1, b1, (const int*)ei, n_nodes);

    edge_mma_kernel<<<592, 128>>>(ei, ea, W1, gamma, beta, W2, b2,
                                  out, n_edges, n_wtiles);
}

// round 13
// speedup vs baseline: 1.3400x; 1.3400x over previous
#include <cuda_runtime.h>
#include <cuda_bf16.h>
#include <math.h>

// ===========================================================================
// MPConv via mma.sync bf16 (compute_103-safe):
//   node precompute: A = x@W1[0:64], B = x@W1[64:128]+b1 (scalar f32x2,
//     double-buffered smem staging, 1 barrier/iter, prefetched LDG)
//   edge (warp-autonomous 32-edge tiles, no in-loop barriers)  [R11 proven]:
//     acc1 = A[i]+B[j] (fragment gather) ; acc1 += ea@W1e (3-term split-bf16)
//     LN per row (2 quad shfl) + branchless A&S erf GELU
//     GEMM2 g@W2+b2 in two N-halves ; red.global.add.v2 scatter
// ===========================================================================

#define MAXN 100000
#define CH   64
#define ED   32

__device__ float g_A[(size_t)MAXN * CH];
__device__ float g_B[(size_t)MAXN * CH];
__device__ int   g_idx64;

typedef unsigned long long u64;
typedef unsigned int       u32;

__device__ __forceinline__ u64 pk2(float lo, float hi) {
    u64 r; asm("mov.b64 %0, {%1,%2};" : "=l"(r) : "f"(lo), "f"(hi)); return r;
}
__device__ __forceinline__ void unpk2(u64 v, float& lo, float& hi) {
    asm("mov.b64 {%0,%1}, %2;" : "=f"(lo), "=f"(hi) : "l"(v));
}
__device__ __forceinline__ u64 fma2(u64 a, u64 b, u64 c) {
    u64 d; asm("fma.rn.f32x2 %0, %1, %2, %3;" : "=l"(d) : "l"(a), "l"(b), "l"(c));
    return d;
}
__device__ __forceinline__ u64 add2(u64 a, u64 b) {
    u64 d; asm("add.rn.f32x2 %0, %1, %2;" : "=l"(d) : "l"(a), "l"(b));
    return d;
}
__device__ __forceinline__ float hsum2(u64 v) { float a, b; unpk2(v, a, b); return a + b; }

__device__ __forceinline__ void red2(float* p, float x, float y) {
    asm volatile("red.global.add.v2.f32 [%0], {%1,%2};"
                 :: "l"(p), "f"(x), "f"(y) : "memory");
}
__device__ __forceinline__ void split1(float v, __nv_bfloat16& h, __nv_bfloat16& l) {
    h = __float2bfloat16_rn(v);
    l = __float2bfloat16_rn(v - __bfloat162float(h));
}
__device__ __forceinline__ u32 pkbf(__nv_bfloat16 a, __nv_bfloat16 b) {
    __nv_bfloat162 t(a, b); return *(u32*)&t;
}
__device__ __forceinline__ u32 hi_pair(float x, float y) {
    u32 r;
    asm("prmt.b32 %0, %1, %2, 0x7632;"
        : "=r"(r) : "r"(__float_as_uint(x)), "r"(__float_as_uint(y)));
    return r;
}
__device__ __forceinline__ u32 lo_pair(float x, float y) {
    float lx = x - __uint_as_float(__float_as_uint(x) & 0xFFFF0000u);
    float ly = y - __uint_as_float(__float_as_uint(y) & 0xFFFF0000u);
    u32 r;
    asm("cvt.rn.bf16x2.f32 %0, %1, %2;" : "=r"(r) : "f"(ly), "f"(lx));
    return r;
}

// Branchless GELU, A&S 7.1.26 erf (|eps| <= 1.5e-7 abs).
__device__ __forceinline__ float gelu_fast(float x) {
    const float axo = fabsf(x);
    const float ax  = axo * 0.70710678118654752440f;
    float t;
    asm("rcp.approx.f32 %0, %1;" : "=f"(t) : "f"(fmaf(0.3275911f, ax, 1.0f)));
    float p = fmaf(1.061405429f, t, -1.453152027f);
    p = fmaf(p, t, 1.421413741f);
    p = fmaf(p, t, -0.284496736f);
    p = fmaf(p, t, 0.254829592f);
    p = p * t;
    float ex;
    asm("ex2.approx.f32 %0, %1;"
        : "=f"(ex) : "f"(ax * ax * -1.4426950408889634f));
    const float er = fmaf(-p, ex, 1.0f);
    return fmaf(0.5f * axo, er, 0.5f * x);
}

__device__ __forceinline__ void mma16816(float* c, const u32* a, const u32* b) {
    asm volatile(
        "mma.sync.aligned.m16n8k16.row.col.f32.bf16.bf16.f32 "
        "{%0,%1,%2,%3}, {%4,%5,%6,%7}, {%8,%9}, {%0,%1,%2,%3};"
        : "+f"(c[0]), "+f"(c[1]), "+f"(c[2]), "+f"(c[3])
        : "r"(a[0]), "r"(a[1]), "r"(a[2]), "r"(a[3]), "r"(b[0]), "r"(b[1]));
}

// ---------------------------------------------------------------------------
// Node precompute v3: double-buffered smem staging, 1 barrier/iter,
// next x row prefetched before the barrier so DRAM latency overlaps compute.
// 256 thr = 2 nodes x {A,B} x 64 ch; 64 weight regs/thread.
// ---------------------------------------------------------------------------
__global__ __launch_bounds__(256) void node_pre_kernel(
    const float* __restrict__ x, const float* __restrict__ W1,
    const float* __restrict__ b1, const int* __restrict__ ei, int n_nodes)
{
    const int t = threadIdx.x;
    const int c   = t & 63;
    const int ab  = (t >> 6) & 1;
    const int grp = t >> 7;

    if (blockIdx.x == 0) {
        int ok = 1;
        for (int q = t; q < 1024; q += blockDim.x)
            if (ei[2 * q + 1] != 0) ok = 0;
        ok = __syncthreads_and(ok);
        if (t == 0) g_idx64 = ok;
    }

    const int kofs = ab ? 64 : 0;
    u64 w[32];
#pragma unroll
    for (int q = 0; q < 32; q++)
        w[q] = pk2(W1[(kofs + 2 * q) * CH + c], W1[(kofs + 2 * q + 1) * CH + c]);
    const float bias = ab ? b1[c] : 0.0f;
    float* dst = ab ? g_B : g_A;

    __shared__ __align__(16) float xs[2][2][CH];   // [buf][grp][c]

    const int step = gridDim.x * 2;

    // prologue: load first row into registers (ab==0 threads stage)
    float cur = 0.0f;
    {
        int node = blockIdx.x * 2 + grp;
        if (ab == 0 && node < n_nodes) cur = x[(size_t)node * CH + c];
    }

    int buf = 0;
    for (int n0 = blockIdx.x * 2; n0 < n_nodes; n0 += step) {
        const int node = n0 + grp;
        if (ab == 0) xs[buf][grp][c] = cur;

        // prefetch next iteration's row BEFORE the barrier
        float nxt = 0.0f;
        {
            int nn = n0 + step + grp;
            if (ab == 0 && nn < n_nodes) nxt = x[(size_t)nn * CH + c];
        }
        __syncthreads();          // staged writes visible; reads from xs[buf]

        if (node < n_nodes) {
            const ulonglong2* xp = (const ulonglong2*)xs[buf][grp];
            u64 a0 = 0ull, a1 = 0ull;
#pragma unroll
            for (int q = 0; q < 16; q++) {
                ulonglong2 xv = xp[q];
                a0 = fma2(xv.x, w[2 * q],     a0);
                a1 = fma2(xv.y, w[2 * q + 1], a1);
            }
            dst[(size_t)node * CH + c] = hsum2(add2(a0, a1)) + bias;
        }
        cur = nxt;
        buf ^= 1;                 // next write goes to the other buffer
    }
}

// ---------------------------------------------------------------------------
// Edge kernel (R11, proven): 4 warps/block, warp owns 32-edge tiles.
// ---------------------------------------------------------------------------
__global__ void __launch_bounds__(128, 3) edge_mma_kernel(
    const void* __restrict__ ei_raw,
    const float* __restrict__ ea,
    const float* __restrict__ W1,
    const float* __restrict__ gamma, const float* __restrict__ beta,
    const float* __restrict__ W2, const float* __restrict__ b2,
    float* __restrict__ out, int n_edges, int n_wtiles)
{
    // Weight B-fragment pairs as u64 words: [4*kt+tq][n], row pad 72.
    __shared__ uint2 sW1H64[8][72],  sW1L64[8][72];
    __shared__ uint2 sW2H64[16][72], sW2L64[16][72];
    __shared__ float sgm[64], sbt[64], sb2v[64];

    const int tid = threadIdx.x;
    for (int idx = tid; idx < 64 * 8; idx += 128) {        // W1 edge part
        int n = idx >> 3, kg = idx & 7;
        int kt = kg >> 2, t4 = kg & 3;
        int plo = 8 * kt + t4, phi = plo + 4;
        __nv_bfloat16 ha, la, hb, lb;
        split1(W1[(size_t)(128 + 2 * plo) * CH + n], ha, la);
        split1(W1[(size_t)(128 + 2 * plo + 1) * CH + n], hb, lb);
        u32 Hlo = pkbf(ha, hb), Llo = pkbf(la, lb);
        split1(W1[(size_t)(128 + 2 * phi) * CH + n], ha, la);
        split1(W1[(size_t)(128 + 2 * phi + 1) * CH + n], hb, lb);
        sW1H64[kg][n] = make_uint2(Hlo, pkbf(ha, hb));
        sW1L64[kg][n] = make_uint2(Llo, pkbf(la, lb));
    }
    for (int idx = tid; idx < 64 * 16; idx += 128) {       // W2
        int n = idx >> 4, kg = idx & 15;
        int kt = kg >> 2, t4 = kg & 3;
        int plo = 8 * kt + t4, phi = plo + 4;
        __nv_bfloat16 ha, la, hb, lb;
        split1(W2[(size_t)(2 * plo) * CH + n], ha, la);
        split1(W2[(size_t)(2 * plo + 1) * CH + n], hb, lb);
        u32 Hlo = pkbf(ha, hb), Llo = pkbf(la, lb);
        split1(W2[(size_t)(2 * phi) * CH + n], ha, la);
        split1(W2[(size_t)(2 * phi + 1) * CH + n], hb, lb);
        sW2H64[kg][n] = make_uint2(Hlo, pkbf(ha, hb));
        sW2L64[kg][n] = make_uint2(Llo, pkbf(la, lb));
    }
    if (tid < 64) { sgm[tid] = gamma[tid]; sbt[tid] = beta[tid]; sb2v[tid] = b2[tid]; }
    __syncthreads();

    const int wid = tid >> 5, lane = tid & 31;
    const int q = lane >> 2, tq = lane & 3;
    const int flag64 = g_idx64;
    const long long* ei64 = (const long long*)ei_raw;
    const int*       ei32 = (const int*)ei_raw;
    const int wstep = gridDim.x * 4;

    auto ldidx = [&](int wtt, int* I, int* J) {
#pragma unroll
        for (int r4 = 0; r4 < 4; r4++) {
            int row = ((r4 >> 1) << 4) + ((r4 & 1) << 3) + q;
            long long e = (long long)wtt * 32 + row;
            if (wtt >= n_wtiles || e >= n_edges) e = 0;
            if (flag64) { I[r4] = (int)ei64[e]; J[r4] = (int)ei64[(size_t)n_edges + e]; }
            else        { I[r4] = ei32[e];      J[r4] = ei32[(size_t)n_edges + e]; }
        }
    };

    int wt = blockIdx.x * 4 + wid;
    int iv[4], jv[4];
    ldidx(wt, iv, jv);

    for (; wt < n_wtiles; wt += wstep) {
        const int eb = wt * 32;

        // ---- acc1 init = s = A[i]+B[j] (fragment-layout gather) ----------
        float acc[2][8][4];
#pragma unroll
        for (int mt = 0; mt < 2; mt++) {
            const float2* pa0 = (const float2*)(g_A + (size_t)iv[2 * mt]     * CH);
            const float2* pb0 = (const float2*)(g_B + (size_t)jv[2 * mt]     * CH);
            const float2* pa8 = (const float2*)(g_A + (size_t)iv[2 * mt + 1] * CH);
            const float2* pb8 = (const float2*)(g_B + (size_t)jv[2 * mt + 1] * CH);
#pragma unroll
            for (int nt = 0; nt < 8; nt++) {
                float2 x0 = pa0[4 * nt + tq], y0 = pb0[4 * nt + tq];
                float2 x8 = pa8[4 * nt + tq], y8 = pb8[4 * nt + tq];
                acc[mt][nt][0] = x0.x + y0.x;  acc[mt][nt][1] = x0.y + y0.y;
                acc[mt][nt][2] = x8.x + y8.x;  acc[mt][nt][3] = x8.y + y8.y;
            }
        }

        // ---- ea A-fragments (fast hi/lo split) ---------------------------
        u32 eH[2][2][4], eL[2][2][4];
#pragma unroll
        for (int mt = 0; mt < 2; mt++)
#pragma unroll
            for (int g8 = 0; g8 < 2; g8++) {
                int row = mt * 16 + g8 * 8 + q;
                int e = eb + row; if (e >= n_edges) e = 0;
                const float2* pe = (const float2*)(ea + (size_t)e * ED);
#pragma unroll
                for (int kt = 0; kt < 2; kt++)
#pragma unroll
                    for (int gr = 0; gr < 2; gr++) {
                        float2 v = pe[8 * kt + 4 * gr + tq];
                        eH[mt][kt][gr * 2 + g8] = hi_pair(v.x, v.y);
                        eL[mt][kt][gr * 2 + g8] = lo_pair(v.x, v.y);
                    }
            }

        // ---- prefetch next tile's indices --------------------------------
        int ivn[4], jvn[4];
        ldidx(wt + wstep, ivn, jvn);

        // ---- GEMM1: acc += ea @ W1e (3-term split) -----------------------
#pragma unroll
        for (int kt = 0; kt < 2; kt++)
#pragma unroll
            for (int nt = 0; nt < 8; nt++) {
                uint2 BH = sW1H64[4 * kt + tq][8 * nt + q];
                uint2 BL = sW1L64[4 * kt + tq][8 * nt + q];
                u32 bH[2] = { BH.x, BH.y };
                u32 bL[2] = { BL.x, BL.y };
#pragma unroll
                for (int mt = 0; mt < 2; mt++) {
                    mma16816(acc[mt][nt], eH[mt][kt], bH);
                    mma16816(acc[mt][nt], eH[mt][kt], bL);
                    mma16816(acc[mt][nt], eL[mt][kt], bH);
                }
            }

        // ---- LayerNorm stats: quad reduce (2 shfl) per row ---------------
        float mean[2][2], rstd[2][2];
#pragma unroll
        for (int mt = 0; mt < 2; mt++)
#pragma unroll
            for (int g8 = 0; g8 < 2; g8++) {
                u64 ssp = 0ull;
#pragma unroll
                for (int nt = 0; nt < 8; nt++) {
                    float v0 = acc[mt][nt][2 * g8], v1 = acc[mt][nt][2 * g8 + 1];
                    ssp = add2(ssp, pk2(v0 + v1, fmaf(v0, v0, v1 * v1)));
                }
                ssp = add2(ssp, __shfl_xor_sync(0xffffffffu, ssp, 1));
                ssp = add2(ssp, __shfl_xor_sync(0xffffffffu, ssp, 2));
                float s, s2; unpk2(ssp, s, s2);
                float mu = s * (1.0f / 64.0f);
                mean[mt][g8] = mu;
                rstd[mt][g8] = rsqrtf(s2 * (1.0f / 64.0f) - mu * mu + 1e-5f);
            }

        // ---- LN + fast GELU + fast split -> GEMM2 A-fragments ------------
        u32 gh[2][2][8], gl[2][2][8];
#pragma unroll
        for (int mt = 0; mt < 2; mt++)
#pragma unroll
            for (int nt = 0; nt < 8; nt++) {
                float2 gm = *(const float2*)&sgm[8 * nt + 2 * tq];
                float2 bt = *(const float2*)&sbt[8 * nt + 2 * tq];
#pragma unroll
                for (int g8 = 0; g8 < 2; g8++) {
                    float h0 = fmaf((acc[mt][nt][2 * g8]     - mean[mt][g8]) * rstd[mt][g8], gm.x, bt.x);
                    float h1 = fmaf((acc[mt][nt][2 * g8 + 1] - mean[mt][g8]) * rstd[mt][g8], gm.y, bt.y);
                    float e0 = gelu_fast(h0);
                    float e1 = gelu_fast(h1);
                    gh[mt][g8][nt] = hi_pair(e0, e1);
                    gl[mt][g8][nt] = lo_pair(e0, e1);
                }
            }

        // ---- GEMM2 + scatter in two sequential N-halves ------------------
#pragma unroll 1
        for (int half = 0; half < 2; half++) {
            float acc2[2][4][4];
#pragma unroll
            for (int mt = 0; mt < 2; mt++)
#pragma unroll
                for (int n4 = 0; n4 < 4; n4++) {
                    int nt = half * 4 + n4;
                    float2 b2p = *(const float2*)&sb2v[8 * nt + 2 * tq];
                    acc2[mt][n4][0] = b2p.x; acc2[mt][n4][1] = b2p.y;
                    acc2[mt][n4][2] = b2p.x; acc2[mt][n4][3] = b2p.y;
                }
#pragma unroll
            for (int kt = 0; kt < 4; kt++)
#pragma unroll
                for (int n4 = 0; n4 < 4; n4++) {
                    int nt = half * 4 + n4;
                    int nr = 8 * nt + q;
                    uint2 BH = sW2H64[4 * kt + tq][nr];
                    uint2 BL = sW2L64[4 * kt + tq][nr];
                    u32 bH[2] = { BH.x, BH.y };
                    u32 bL[2] = { BL.x, BL.y };
#pragma unroll
                    for (int mt = 0; mt < 2; mt++) {
                        u32 aH[4] = { gh[mt][0][2 * kt], gh[mt][1][2 * kt],
                                      gh[mt][0][2 * kt + 1], gh[mt][1][2 * kt + 1] };
                        u32 aL[4] = { gl[mt][0][2 * kt], gl[mt][1][2 * kt],
                                      gl[mt][0][2 * kt + 1], gl[mt][1][2 * kt + 1] };
                        mma16816(acc2[mt][n4], aH, bH);
                        mma16816(acc2[mt][n4], aH, bL);
                        mma16816(acc2[mt][n4], aL, bH);
                    }
                }
#pragma unroll
            for (int mt = 0; mt < 2; mt++)
#pragma unroll
                for (int g8 = 0; g8 < 2; g8++) {
                    int row = mt * 16 + g8 * 8 + q;
                    int e = eb + row;
                    if (e < n_edges) {
                        float* op = out + (size_t)jv[2 * mt + g8] * CH + 2 * tq;
#pragma unroll
                        for (int n4 = 0; n4 < 4; n4++)
                            red2(op + 8 * (half * 4 + n4),
                                 acc2[mt][n4][2 * g8], acc2[mt][n4][2 * g8 + 1]);
                    }
                }
        }

        // ---- rotate prefetched indices -----------------------------------
#pragma unroll
        for (int r4 = 0; r4 < 4; r4++) { iv[r4] = ivn[r4]; jv[r4] = jvn[r4]; }
    }
}

// ---------------------------------------------------------------------------
// Inputs: x[N,64] f32, edge_index[2,E] (i32/i64), edge_attr[E,32] f32,
// W1[160,64], b1[64], gamma[64], beta[64], W2[64,64], b2[64]. Out [N,64] f32.
// ---------------------------------------------------------------------------
extern "C" void kernel_launch(void* const* d_in, const int* in_sizes, int n_in,
                              void* d_out, int out_size)
{
    const float* x     = (const float*)d_in[0];
    const void*  ei    = d_in[1];
    const float* ea    = (const float*)d_in[2];
    const float* W1    = (const float*)d_in[3];
    const float* b1    = (const float*)d_in[4];
    const float* gamma = (const float*)d_in[5];
    const float* beta  = (const float*)d_in[6];
    const float* W2    = (const float*)d_in[7];
    const float* b2    = (const float*)d_in[8];
    float* out = (float*)d_out;

    const int n_nodes  = in_sizes[0] / CH;
    const int n_edges  = in_sizes[2] / ED;
    const int n_wtiles = (n_edges + 31) / 32;
    if (n_nodes > MAXN) return;

    cudaMemsetAsync(d_out, 0, (size_t)out_size * sizeof(float));

    node_pre_kernel<<<592, 256>>>(x, W1, b1, (const int*)ei, n_nodes);

    edge_mma_kernel<<<444, 128>>>(ei, ea, W1, gamma, beta, W2, b2,
                                  out, n_edges, n_wtiles);
}